// round 2
// baseline (speedup 1.0000x reference)
#include <cuda_runtime.h>
#include <math.h>

#define N_NODES 20000
#define H 256
#define R_RBF 64
#define E_EDGES 320000

// ---------------- scratch (device globals; no allocation at launch) ----------
__device__ float g_xnorm[(size_t)N_NODES * H];
__device__ float g_q[(size_t)N_NODES * H];
__device__ float g_k[(size_t)N_NODES * H];
__device__ float g_v[(size_t)N_NODES * H];
__device__ float g_agg[(size_t)N_NODES * H];
__device__ float g_dkv[(size_t)E_EDGES * 2 * H];   // [E][512]: dk | dv
__device__ int   g_src[E_EDGES];
__device__ int   g_dst[E_EDGES];
__device__ int   g_is64;

// ---------------- edge_index dtype detection + conversion -------------------
// jnp.int64 silently downcasts to int32 when JAX x64 is disabled. Detect which
// layout we actually got: for little-endian int64 with values < 2^31, every odd
// int32 word is zero.
__global__ void detect_idx_kernel(const int* __restrict__ p)
{
    if (threadIdx.x == 0 && blockIdx.x == 0) {
        int all_zero = 1;
        for (int i = 0; i < 64; i++)
            if (p[2 * i + 1] != 0) { all_zero = 0; break; }
        g_is64 = all_zero;
    }
}

__global__ void convert_idx_kernel(const void* __restrict__ p)
{
    int e = blockIdx.x * blockDim.x + threadIdx.x;
    if (e >= E_EDGES) return;
    if (g_is64) {
        const long long* q = (const long long*)p;
        g_src[e] = (int)q[e];
        g_dst[e] = (int)q[E_EDGES + e];
    } else {
        const int* q = (const int*)p;
        g_src[e] = q[e];
        g_dst[e] = q[E_EDGES + e];
    }
}

// ---------------- LayerNorm (+ zero agg) ------------------------------------
__global__ void ln_kernel(const float* __restrict__ x,
                          const float* __restrict__ g,
                          const float* __restrict__ b)
{
    int n = blockIdx.x;
    int h = threadIdx.x;                 // 256 threads
    float v = x[(size_t)n * H + h];
    float s1 = v, s2 = v * v;
    #pragma unroll
    for (int o = 16; o; o >>= 1) {
        s1 += __shfl_xor_sync(0xffffffffu, s1, o);
        s2 += __shfl_xor_sync(0xffffffffu, s2, o);
    }
    __shared__ float sm1[8], sm2[8];
    int wid = h >> 5;
    if ((h & 31) == 0) { sm1[wid] = s1; sm2[wid] = s2; }
    __syncthreads();
    float t1 = 0.f, t2 = 0.f;
    #pragma unroll
    for (int i = 0; i < 8; i++) { t1 += sm1[i]; t2 += sm2[i]; }
    float mu  = t1 * (1.0f / H);
    float var = t2 * (1.0f / H) - mu * mu;
    float xn = (v - mu) * rsqrtf(var + 1e-5f) * g[h] + b[h];
    g_xnorm[(size_t)n * H + h] = xn;
    g_agg[(size_t)n * H + h]  = 0.f;
}

// ---------------- generic SGEMM: C[row, col0+col] = A[M,K] @ W[Nout,K]^T -----
// EPI: 0 = +bias, 1 = silu(+bias), 2 = +bias +residual
template<int EPI>
__global__ void __launch_bounds__(256)
gemm_nt(const float* __restrict__ A, int M, int K,
        const float* __restrict__ W, const float* __restrict__ bias,
        float* __restrict__ C, int ldc, int col0,
        const float* __restrict__ residual)
{
    const int BM = 128, BN = 128, BK = 32;
    __shared__ float As[BK][BM + 4];
    __shared__ float Ws[BK][BN + 4];

    int tid = threadIdx.x;
    int tx = tid & 15;          // 16 threads over N
    int ty = tid >> 4;          // 16 threads over M
    int row0 = blockIdx.x * BM;
    int nb0  = blockIdx.y * BN;

    float acc[8][8];
    #pragma unroll
    for (int i = 0; i < 8; i++)
        #pragma unroll
        for (int j = 0; j < 8; j++) acc[i][j] = 0.f;

    int lc = tid & 7;           // float4 column within BK
    int lr = tid >> 3;          // 0..31 row within tile

    for (int k0 = 0; k0 < K; k0 += BK) {
        #pragma unroll
        for (int i = 0; i < 4; i++) {
            int m = lr + i * 32;
            int gr = row0 + m;
            float4 va = (gr < M) ? *(const float4*)&A[(size_t)gr * K + k0 + lc * 4]
                                 : make_float4(0.f, 0.f, 0.f, 0.f);
            As[lc * 4 + 0][m] = va.x; As[lc * 4 + 1][m] = va.y;
            As[lc * 4 + 2][m] = va.z; As[lc * 4 + 3][m] = va.w;

            int n = lr + i * 32;
            float4 vw = *(const float4*)&W[(size_t)(nb0 + n) * K + k0 + lc * 4];
            Ws[lc * 4 + 0][n] = vw.x; Ws[lc * 4 + 1][n] = vw.y;
            Ws[lc * 4 + 2][n] = vw.z; Ws[lc * 4 + 3][n] = vw.w;
        }
        __syncthreads();
        #pragma unroll
        for (int k = 0; k < BK; k++) {
            float a[8], bb[8];
            *(float4*)&a[0]  = *(const float4*)&As[k][ty * 8];
            *(float4*)&a[4]  = *(const float4*)&As[k][ty * 8 + 4];
            *(float4*)&bb[0] = *(const float4*)&Ws[k][tx * 8];
            *(float4*)&bb[4] = *(const float4*)&Ws[k][tx * 8 + 4];
            #pragma unroll
            for (int i = 0; i < 8; i++)
                #pragma unroll
                for (int j = 0; j < 8; j++)
                    acc[i][j] += a[i] * bb[j];
        }
        __syncthreads();
    }

    float bv[8];
    #pragma unroll
    for (int j = 0; j < 8; j++) bv[j] = bias[nb0 + tx * 8 + j];

    #pragma unroll
    for (int i = 0; i < 8; i++) {
        int row = row0 + ty * 8 + i;
        if (row < M) {
            float out[8];
            #pragma unroll
            for (int j = 0; j < 8; j++) {
                float t = acc[i][j] + bv[j];
                if (EPI == 1) t = t / (1.f + __expf(-t));          // silu
                if (EPI == 2) t += residual[(size_t)row * ldc + col0 + nb0 + tx * 8 + j];
                out[j] = t;
            }
            float4* cp = (float4*)&C[(size_t)row * ldc + col0 + nb0 + tx * 8];
            cp[0] = *(float4*)&out[0];
            cp[1] = *(float4*)&out[4];
        }
    }
}

// ---------------- edge attention + scatter (warp per edge) ------------------
__global__ void edge_attn_kernel(const float* __restrict__ ew)
{
    int gw = (blockIdx.x * blockDim.x + threadIdx.x) >> 5;
    if (gw >= E_EDGES) return;
    int lane = threadIdx.x & 31;
    int e = gw;
    int src = g_src[e];
    int dst = g_dst[e];

    const float4* qr  = (const float4*)(g_q + (size_t)dst * H);
    const float4* kr  = (const float4*)(g_k + (size_t)src * H);
    const float4* dk4 = (const float4*)(g_dkv + (size_t)e * (2 * H));

    float4 qa = qr[lane],      ka = kr[lane],      da = dk4[lane];
    float4 qb = qr[lane + 32], kb = kr[lane + 32], db = dk4[lane + 32];
    float part = qa.x * ka.x * da.x + qa.y * ka.y * da.y
               + qa.z * ka.z * da.z + qa.w * ka.w * da.w
               + qb.x * kb.x * db.x + qb.y * kb.y * db.y
               + qb.z * kb.z * db.z + qb.w * kb.w * db.w;
    #pragma unroll
    for (int o = 16; o; o >>= 1) part += __shfl_xor_sync(0xffffffffu, part, o);

    float r = ew[e];
    float cut = (r < 5.0f) ? 0.5f * (cosf(r * 0.62831853071795864769f) + 1.0f) : 0.0f;
    float s = part / (1.f + __expf(-part)) * cut;   // silu(attn) * cutoff

    const float4* vr  = (const float4*)(g_v + (size_t)src * H);
    const float4* dv4 = dk4 + (H / 4);              // dv at +256 floats
    float* aggrow = g_agg + (size_t)dst * H;

    #pragma unroll
    for (int half = 0; half < 2; half++) {
        int i = lane + half * 32;
        float4 vv = vr[i], dm = dv4[i];
        float mx = vv.x * dm.x * s;
        float my = vv.y * dm.y * s;
        float mz = vv.z * dm.z * s;
        float mw = vv.w * dm.w * s;
        asm volatile("red.global.add.v4.f32 [%0], {%1, %2, %3, %4};"
                     :: "l"(aggrow + i * 4), "f"(mx), "f"(my), "f"(mz), "f"(mw)
                     : "memory");
    }
}

// ---------------- launch -----------------------------------------------------
extern "C" void kernel_launch(void* const* d_in, const int* in_sizes, int n_in,
                              void* d_out, int out_size)
{
    const float* x    = (const float*)d_in[0];
    const void*  eidx = (const void*)d_in[1];
    const float* ew   = (const float*)d_in[2];
    const float* ea   = (const float*)d_in[3];
    const float* ln_g = (const float*)d_in[4];
    const float* ln_b = (const float*)d_in[5];
    const float* Wq   = (const float*)d_in[6],  *bq  = (const float*)d_in[7];
    const float* Wk   = (const float*)d_in[8],  *bk  = (const float*)d_in[9];
    const float* Wv   = (const float*)d_in[10], *bv  = (const float*)d_in[11];
    const float* Wo   = (const float*)d_in[12], *bo  = (const float*)d_in[13];
    const float* Wdk  = (const float*)d_in[14], *bdk = (const float*)d_in[15];
    const float* Wdv  = (const float*)d_in[16], *bdv = (const float*)d_in[17];
    float* out = (float*)d_out;

    float *xn, *q, *k, *v, *agg, *dkv;
    cudaGetSymbolAddress((void**)&xn,  g_xnorm);
    cudaGetSymbolAddress((void**)&q,   g_q);
    cudaGetSymbolAddress((void**)&k,   g_k);
    cudaGetSymbolAddress((void**)&v,   g_v);
    cudaGetSymbolAddress((void**)&agg, g_agg);
    cudaGetSymbolAddress((void**)&dkv, g_dkv);

    // 0. edge_index dtype detection + int32 conversion
    detect_idx_kernel<<<1, 32>>>((const int*)eidx);
    convert_idx_kernel<<<(E_EDGES + 255) / 256, 256>>>(eidx);

    // 1. LayerNorm + zero agg
    ln_kernel<<<N_NODES, 256>>>(x, ln_g, ln_b);

    // 2. q, k, v = xn @ W^T + b
    dim3 gq((N_NODES + 127) / 128, 2);
    gemm_nt<0><<<gq, 256>>>(xn, N_NODES, H, Wq, bq, q, H, 0, nullptr);
    gemm_nt<0><<<gq, 256>>>(xn, N_NODES, H, Wk, bk, k, H, 0, nullptr);
    gemm_nt<0><<<gq, 256>>>(xn, N_NODES, H, Wv, bv, v, H, 0, nullptr);

    // 3. dk, dv = silu(edge_attr @ W^T + b)  -> g_dkv [E][512]
    dim3 ge(E_EDGES / 128, 2);
    gemm_nt<1><<<ge, 256>>>(ea, E_EDGES, R_RBF, Wdk, bdk, dkv, 2 * H, 0, nullptr);
    gemm_nt<1><<<ge, 256>>>(ea, E_EDGES, R_RBF, Wdv, bdv, dkv, 2 * H, H, nullptr);

    // 4. per-edge attention + scatter into agg
    edge_attn_kernel<<<E_EDGES / 8, 256>>>(ew);

    // 5. out = agg @ Wo^T + bo + x
    gemm_nt<2><<<gq, 256>>>(agg, N_NODES, H, Wo, bo, out, H, 0, x);
}

// round 3
// speedup vs baseline: 1.0310x; 1.0310x over previous
#include <cuda_runtime.h>
#include <math.h>

#define N_NODES 20000
#define H 256
#define R_RBF 64
#define E_EDGES 320000

// ---------------- scratch (device globals; no allocation at launch) ----------
__device__ float g_xnorm[(size_t)N_NODES * H];
__device__ float g_q[(size_t)N_NODES * H];
__device__ float g_k[(size_t)N_NODES * H];
__device__ float g_v[(size_t)N_NODES * H];
__device__ float g_agg[(size_t)N_NODES * H];
__device__ float g_attn[E_EDGES];
__device__ float g_s[E_EDGES];
__device__ int   g_src[E_EDGES];
__device__ int   g_dst[E_EDGES];
__device__ int   g_is64;

// ---------------- packed fp32x2 helpers (FFMA2 path, PTX-only) ---------------
__device__ __forceinline__ void fma2(unsigned long long& d,
                                     unsigned long long a,
                                     unsigned long long b)
{
    asm("fma.rn.f32x2 %0, %1, %2, %0;" : "+l"(d) : "l"(a), "l"(b));
}
__device__ __forceinline__ unsigned long long dup2(float x)
{
    unsigned long long r;
    asm("mov.b64 %0, {%1, %1};" : "=l"(r) : "f"(x));
    return r;
}
__device__ __forceinline__ void unpack2(unsigned long long v, float& lo, float& hi)
{
    asm("mov.b64 {%0, %1}, %2;" : "=f"(lo), "=f"(hi) : "l"(v));
}

// ---------------- edge_index dtype detection + conversion -------------------
__global__ void detect_idx_kernel(const int* __restrict__ p)
{
    if (threadIdx.x == 0 && blockIdx.x == 0) {
        int all_zero = 1;
        for (int i = 0; i < 64; i++)
            if (p[2 * i + 1] != 0) { all_zero = 0; break; }
        g_is64 = all_zero;
    }
}

__global__ void convert_idx_kernel(const void* __restrict__ p)
{
    int e = blockIdx.x * blockDim.x + threadIdx.x;
    if (e >= E_EDGES) return;
    if (g_is64) {
        const long long* q = (const long long*)p;
        g_src[e] = (int)q[e];
        g_dst[e] = (int)q[E_EDGES + e];
    } else {
        const int* q = (const int*)p;
        g_src[e] = q[e];
        g_dst[e] = q[E_EDGES + e];
    }
    g_attn[e] = 0.f;
}

// ---------------- LayerNorm (+ zero agg) ------------------------------------
__global__ void ln_kernel(const float* __restrict__ x,
                          const float* __restrict__ g,
                          const float* __restrict__ b)
{
    int n = blockIdx.x;
    int h = threadIdx.x;                 // 256 threads
    float v = x[(size_t)n * H + h];
    float s1 = v, s2 = v * v;
    #pragma unroll
    for (int o = 16; o; o >>= 1) {
        s1 += __shfl_xor_sync(0xffffffffu, s1, o);
        s2 += __shfl_xor_sync(0xffffffffu, s2, o);
    }
    __shared__ float sm1[8], sm2[8];
    int wid = h >> 5;
    if ((h & 31) == 0) { sm1[wid] = s1; sm2[wid] = s2; }
    __syncthreads();
    float t1 = 0.f, t2 = 0.f;
    #pragma unroll
    for (int i = 0; i < 8; i++) { t1 += sm1[i]; t2 += sm2[i]; }
    float mu  = t1 * (1.0f / H);
    float var = t2 * (1.0f / H) - mu * mu;
    float xn = (v - mu) * rsqrtf(var + 1e-5f) * g[h] + b[h];
    g_xnorm[(size_t)n * H + h] = xn;
    g_agg[(size_t)n * H + h]  = 0.f;
}

// ---------------- SGEMM: C = A[M,K] @ W[Nout,K]^T, FFMA2 inner loop ---------
// EPI 0: C = acc + bias
// EPI 2: C = acc + bias + residual
// EPI 3: edge-attn partial: atomicAdd(attn[e], sum_j silu(acc+b)*q[dst]*k[src])
// EPI 4: edge scatter: red.add(agg[dst], silu(acc+b) * s[e] * v[src])
template<int EPI>
__global__ void __launch_bounds__(256)
gemm_nt(const float* __restrict__ A, int M, int K,
        const float* __restrict__ W, const float* __restrict__ bias,
        float* __restrict__ C, int ldc,
        const float* __restrict__ residual)
{
    const int BM = 128, BN = 128, BK = 32;
    __shared__ float As[BK][BM + 4];
    __shared__ float Ws[BK][BN + 4];

    int tid = threadIdx.x;
    int tx = tid & 15;          // 16 threads over N (columns)
    int ty = tid >> 4;          // 16 threads over M (rows)
    int row0 = blockIdx.x * BM;
    int nb0  = blockIdx.y * BN;

    unsigned long long acc2[8][4];
    #pragma unroll
    for (int i = 0; i < 8; i++)
        #pragma unroll
        for (int j = 0; j < 4; j++) acc2[i][j] = 0ull;

    int lc = tid & 7;           // float4 column within BK
    int lr = tid >> 3;          // 0..31 row within tile

    for (int k0 = 0; k0 < K; k0 += BK) {
        #pragma unroll
        for (int i = 0; i < 4; i++) {
            int m = lr + i * 32;
            int gr = row0 + m;
            float4 va = (gr < M) ? *(const float4*)&A[(size_t)gr * K + k0 + lc * 4]
                                 : make_float4(0.f, 0.f, 0.f, 0.f);
            As[lc * 4 + 0][m] = va.x; As[lc * 4 + 1][m] = va.y;
            As[lc * 4 + 2][m] = va.z; As[lc * 4 + 3][m] = va.w;

            int n = lr + i * 32;
            float4 vw = *(const float4*)&W[(size_t)(nb0 + n) * K + k0 + lc * 4];
            Ws[lc * 4 + 0][n] = vw.x; Ws[lc * 4 + 1][n] = vw.y;
            Ws[lc * 4 + 2][n] = vw.z; Ws[lc * 4 + 3][n] = vw.w;
        }
        __syncthreads();
        #pragma unroll
        for (int k = 0; k < BK; k++) {
            float a[8];
            *(float4*)&a[0] = *(const float4*)&As[k][ty * 8];
            *(float4*)&a[4] = *(const float4*)&As[k][ty * 8 + 4];
            unsigned long long b2[4];
            const unsigned long long* bp =
                (const unsigned long long*)&Ws[k][tx * 8];
            b2[0] = bp[0]; b2[1] = bp[1]; b2[2] = bp[2]; b2[3] = bp[3];
            #pragma unroll
            for (int i = 0; i < 8; i++) {
                unsigned long long ad = dup2(a[i]);
                fma2(acc2[i][0], ad, b2[0]);
                fma2(acc2[i][1], ad, b2[1]);
                fma2(acc2[i][2], ad, b2[2]);
                fma2(acc2[i][3], ad, b2[3]);
            }
        }
        __syncthreads();
    }

    float bv[8];
    #pragma unroll
    for (int j = 0; j < 8; j++) bv[j] = bias[nb0 + tx * 8 + j];

    if (EPI == 0 || EPI == 2) {
        #pragma unroll
        for (int i = 0; i < 8; i++) {
            int row = row0 + ty * 8 + i;
            if (row < M) {
                float o[8];
                #pragma unroll
                for (int j = 0; j < 4; j++) unpack2(acc2[i][j], o[2*j], o[2*j+1]);
                #pragma unroll
                for (int j = 0; j < 8; j++) {
                    o[j] += bv[j];
                    if (EPI == 2) o[j] += residual[(size_t)row * ldc + nb0 + tx * 8 + j];
                }
                float4* cp = (float4*)&C[(size_t)row * ldc + nb0 + tx * 8];
                cp[0] = *(float4*)&o[0];
                cp[1] = *(float4*)&o[4];
            }
        }
    } else if (EPI == 3) {
        // per-edge attention partial dot
        float red[8];
        #pragma unroll
        for (int i = 0; i < 8; i++) {
            int e  = row0 + ty * 8 + i;
            int sj = g_src[e], di = g_dst[e];
            const float4* qp = (const float4*)(g_q + (size_t)di * H + nb0 + tx * 8);
            const float4* kp = (const float4*)(g_k + (size_t)sj * H + nb0 + tx * 8);
            float4 q0 = qp[0], q1 = qp[1];
            float4 kk0 = kp[0], kk1 = kp[1];
            float o[8];
            #pragma unroll
            for (int j = 0; j < 4; j++) unpack2(acc2[i][j], o[2*j], o[2*j+1]);
            #pragma unroll
            for (int j = 0; j < 8; j++) {
                float t = o[j] + bv[j];
                o[j] = t / (1.f + __expf(-t));          // silu(dk)
            }
            red[i] = o[0]*q0.x*kk0.x + o[1]*q0.y*kk0.y
                   + o[2]*q0.z*kk0.z + o[3]*q0.w*kk0.w
                   + o[4]*q1.x*kk1.x + o[5]*q1.y*kk1.y
                   + o[6]*q1.z*kk1.z + o[7]*q1.w*kk1.w;
        }
        #pragma unroll
        for (int i = 0; i < 8; i++) {
            float v = red[i];
            #pragma unroll
            for (int o = 8; o; o >>= 1) v += __shfl_xor_sync(0xffffffffu, v, o);
            if (tx == 0) atomicAdd(&g_attn[row0 + ty * 8 + i], v);
        }
    } else { // EPI == 4: dv + message scatter
        #pragma unroll
        for (int i = 0; i < 8; i++) {
            int e  = row0 + ty * 8 + i;
            int sj = g_src[e], di = g_dst[e];
            float sc = g_s[e];
            const float4* vp = (const float4*)(g_v + (size_t)sj * H + nb0 + tx * 8);
            float4 v0 = vp[0], v1 = vp[1];
            float o[8];
            #pragma unroll
            for (int j = 0; j < 4; j++) unpack2(acc2[i][j], o[2*j], o[2*j+1]);
            #pragma unroll
            for (int j = 0; j < 8; j++) {
                float t = o[j] + bv[j];
                o[j] = t / (1.f + __expf(-t)) * sc;     // silu(dv) * s
            }
            float* ap = g_agg + (size_t)di * H + nb0 + tx * 8;
            asm volatile("red.global.add.v4.f32 [%0], {%1, %2, %3, %4};"
                         :: "l"(ap), "f"(o[0]*v0.x), "f"(o[1]*v0.y),
                            "f"(o[2]*v0.z), "f"(o[3]*v0.w) : "memory");
            asm volatile("red.global.add.v4.f32 [%0], {%1, %2, %3, %4};"
                         :: "l"(ap + 4), "f"(o[4]*v1.x), "f"(o[5]*v1.y),
                            "f"(o[6]*v1.z), "f"(o[7]*v1.w) : "memory");
        }
    }
}

// ---------------- attn -> s : silu(attn) * cosine cutoff ---------------------
__global__ void attn_post_kernel(const float* __restrict__ ew)
{
    int e = blockIdx.x * blockDim.x + threadIdx.x;
    if (e >= E_EDGES) return;
    float a = g_attn[e];
    float r = ew[e];
    float cut = (r < 5.0f) ? 0.5f * (cosf(r * 0.62831853071795864769f) + 1.0f) : 0.0f;
    g_s[e] = a / (1.f + __expf(-a)) * cut;
}

// ---------------- launch -----------------------------------------------------
extern "C" void kernel_launch(void* const* d_in, const int* in_sizes, int n_in,
                              void* d_out, int out_size)
{
    const float* x    = (const float*)d_in[0];
    const void*  eidx = (const void*)d_in[1];
    const float* ew   = (const float*)d_in[2];
    const float* ea   = (const float*)d_in[3];
    const float* ln_g = (const float*)d_in[4];
    const float* ln_b = (const float*)d_in[5];
    const float* Wq   = (const float*)d_in[6],  *bq  = (const float*)d_in[7];
    const float* Wk   = (const float*)d_in[8],  *bk  = (const float*)d_in[9];
    const float* Wv   = (const float*)d_in[10], *bv  = (const float*)d_in[11];
    const float* Wo   = (const float*)d_in[12], *bo  = (const float*)d_in[13];
    const float* Wdk  = (const float*)d_in[14], *bdk = (const float*)d_in[15];
    const float* Wdv  = (const float*)d_in[16], *bdv = (const float*)d_in[17];
    float* out = (float*)d_out;

    float *xn, *q, *k, *v, *agg;
    cudaGetSymbolAddress((void**)&xn,  g_xnorm);
    cudaGetSymbolAddress((void**)&q,   g_q);
    cudaGetSymbolAddress((void**)&k,   g_k);
    cudaGetSymbolAddress((void**)&v,   g_v);
    cudaGetSymbolAddress((void**)&agg, g_agg);

    // 0. edge_index dtype detection + int32 conversion (+ zero attn)
    detect_idx_kernel<<<1, 32>>>((const int*)eidx);
    convert_idx_kernel<<<(E_EDGES + 255) / 256, 256>>>(eidx);

    // 1. LayerNorm + zero agg
    ln_kernel<<<N_NODES, 256>>>(x, ln_g, ln_b);

    // 2. q, k, v = xn @ W^T + b
    dim3 gq((N_NODES + 127) / 128, 2);
    gemm_nt<0><<<gq, 256>>>(xn, N_NODES, H, Wq, bq, q, H, nullptr);
    gemm_nt<0><<<gq, 256>>>(xn, N_NODES, H, Wk, bk, k, H, nullptr);
    gemm_nt<0><<<gq, 256>>>(xn, N_NODES, H, Wv, bv, v, H, nullptr);

    // 3. fused dk-GEMM + attention dot -> g_attn
    dim3 ge(E_EDGES / 128, 2);
    gemm_nt<3><<<ge, 256>>>(ea, E_EDGES, R_RBF, Wdk, bdk, nullptr, 0, nullptr);

    // 4. s = silu(attn) * cutoff
    attn_post_kernel<<<(E_EDGES + 255) / 256, 256>>>(ew);

    // 5. fused dv-GEMM + message scatter -> g_agg
    gemm_nt<4><<<ge, 256>>>(ea, E_EDGES, R_RBF, Wdv, bdv, nullptr, 0, nullptr);

    // 6. out = agg @ Wo^T + bo + x
    gemm_nt<2><<<gq, 256>>>(agg, N_NODES, H, Wo, bo, out, H, x);
}

// round 4
// speedup vs baseline: 1.5171x; 1.4714x over previous
#include <cuda_runtime.h>
#include <math.h>
#include <stdint.h>

#define N_NODES 20000
#define H 256
#define R_RBF 64
#define E_EDGES 320000

// ---------------- scratch (device globals; no allocation at launch) ----------
__device__ float g_xnorm[(size_t)N_NODES * H];
__device__ float g_q[(size_t)N_NODES * H];
__device__ float g_k[(size_t)N_NODES * H];
__device__ float g_v[(size_t)N_NODES * H];
__device__ float g_agg[(size_t)N_NODES * H];
__device__ float g_attn[E_EDGES];
__device__ float g_s[E_EDGES];
__device__ int   g_src[E_EDGES];
__device__ int   g_dst[E_EDGES];
__device__ int   g_is64;

// ---------------- helpers -----------------------------------------------------
__device__ __forceinline__ uint32_t f2tf32(float x)
{
    uint32_t r;
    asm("cvt.rna.tf32.f32 %0, %1;" : "=r"(r) : "f"(x));
    return r;
}
__device__ __forceinline__ float silu(float t)
{
    return t / (1.f + __expf(-t));
}
__device__ __forceinline__ void mma_tf32(float* d,
                                         const uint32_t* a, const uint32_t* b)
{
    asm volatile(
        "mma.sync.aligned.m16n8k8.row.col.f32.tf32.tf32.f32 "
        "{%0,%1,%2,%3}, {%4,%5,%6,%7}, {%8,%9}, {%0,%1,%2,%3};"
        : "+f"(d[0]), "+f"(d[1]), "+f"(d[2]), "+f"(d[3])
        : "r"(a[0]), "r"(a[1]), "r"(a[2]), "r"(a[3]),
          "r"(b[0]), "r"(b[1]));
}

// ---------------- edge_index dtype detection + conversion -------------------
__global__ void detect_idx_kernel(const int* __restrict__ p)
{
    if (threadIdx.x == 0 && blockIdx.x == 0) {
        int all_zero = 1;
        for (int i = 0; i < 64; i++)
            if (p[2 * i + 1] != 0) { all_zero = 0; break; }
        g_is64 = all_zero;
    }
}

__global__ void convert_idx_kernel(const void* __restrict__ p)
{
    int e = blockIdx.x * blockDim.x + threadIdx.x;
    if (e >= E_EDGES) return;
    if (g_is64) {
        const long long* q = (const long long*)p;
        g_src[e] = (int)q[e];
        g_dst[e] = (int)q[E_EDGES + e];
    } else {
        const int* q = (const int*)p;
        g_src[e] = q[e];
        g_dst[e] = q[E_EDGES + e];
    }
    g_attn[e] = 0.f;
}

// ---------------- LayerNorm (+ zero agg) ------------------------------------
__global__ void ln_kernel(const float* __restrict__ x,
                          const float* __restrict__ g,
                          const float* __restrict__ b)
{
    int n = blockIdx.x;
    int h = threadIdx.x;                 // 256 threads
    float v = x[(size_t)n * H + h];
    float s1 = v, s2 = v * v;
    #pragma unroll
    for (int o = 16; o; o >>= 1) {
        s1 += __shfl_xor_sync(0xffffffffu, s1, o);
        s2 += __shfl_xor_sync(0xffffffffu, s2, o);
    }
    __shared__ float sm1[8], sm2[8];
    int wid = h >> 5;
    if ((h & 31) == 0) { sm1[wid] = s1; sm2[wid] = s2; }
    __syncthreads();
    float t1 = 0.f, t2 = 0.f;
    #pragma unroll
    for (int i = 0; i < 8; i++) { t1 += sm1[i]; t2 += sm2[i]; }
    float mu  = t1 * (1.0f / H);
    float var = t2 * (1.0f / H) - mu * mu;
    float xn = (v - mu) * rsqrtf(var + 1e-5f) * g[h] + b[h];
    g_xnorm[(size_t)n * H + h] = xn;
    g_agg[(size_t)n * H + h]  = 0.f;
}

// ---------------- tf32 tensor-core GEMM: C = A[M,K] @ W[Nout,K]^T ------------
// Block 128x64, 8 warps (2 m x 4 n), warp tile 64x16, mma m16n8k8.
// EPI 0: C = acc + bias
// EPI 2: C = acc + bias + residual
// EPI 3: atomicAdd(attn[e], sum_cols silu(acc+b) * q[dst] * k[src])
// EPI 4: red.add(agg[dst], silu(acc+b) * s[e] * v[src])
template<int EPI>
__global__ void __launch_bounds__(256)
gemm_tf32(const float* __restrict__ A, int M, int K,
          const float* __restrict__ W, const float* __restrict__ bias,
          float* __restrict__ C, int ldc,
          const float* __restrict__ residual)
{
    const int BM = 128, BN = 64, BK = 32;
    __shared__ __align__(16) uint32_t As[BM * BK];
    __shared__ __align__(16) uint32_t Ws[BN * BK];

    int tid  = threadIdx.x;
    int lane = tid & 31;
    int w    = tid >> 5;
    int wm   = (w & 1) * 64;       // warp m offset
    int wn   = (w >> 1) * 16;      // warp n offset
    int g    = lane >> 2;          // group id 0..7
    int t4   = lane & 3;
    int row0 = blockIdx.x * BM;
    int nb0  = blockIdx.y * BN;

    float acc[4][2][4];            // [m-tile][n-tile][frag]
    #pragma unroll
    for (int mt = 0; mt < 4; mt++)
        #pragma unroll
        for (int nt = 0; nt < 2; nt++)
            #pragma unroll
            for (int j = 0; j < 4; j++) acc[mt][nt][j] = 0.f;

    for (int k0 = 0; k0 < K; k0 += BK) {
        // ---- load A tile (128x32): 4 float4 per thread, swizzled ----
        #pragma unroll
        for (int i = 0; i < 4; i++) {
            int slot = tid + i * 256;          // 0..1023
            int r  = slot >> 3;
            int c4 = (slot & 7) * 4;
            int gr = row0 + r;
            float4 v = (gr < M) ? *(const float4*)&A[(size_t)gr * K + k0 + c4]
                                : make_float4(0.f, 0.f, 0.f, 0.f);
            int cs = c4 ^ ((r & 7) << 2);
            uint32_t* p = &As[r * BK + cs];
            p[0] = f2tf32(v.x); p[1] = f2tf32(v.y);
            p[2] = f2tf32(v.z); p[3] = f2tf32(v.w);
        }
        // ---- load W tile (64x32): 2 float4 per thread, swizzled ----
        #pragma unroll
        for (int i = 0; i < 2; i++) {
            int slot = tid + i * 256;          // 0..511
            int r  = slot >> 3;
            int c4 = (slot & 7) * 4;
            float4 v = *(const float4*)&W[(size_t)(nb0 + r) * K + k0 + c4];
            int cs = c4 ^ ((r & 7) << 2);
            uint32_t* p = &Ws[r * BK + cs];
            p[0] = f2tf32(v.x); p[1] = f2tf32(v.y);
            p[2] = f2tf32(v.z); p[3] = f2tf32(v.w);
        }
        __syncthreads();

        #pragma unroll
        for (int ks = 0; ks < 4; ks++) {
            int kb = ks * 8;
            int cL = (kb + t4)     ^ (g << 2);
            int cH = (kb + t4 + 4) ^ (g << 2);
            uint32_t b[2][2];
            #pragma unroll
            for (int nt = 0; nt < 2; nt++) {
                int n = wn + nt * 8 + g;       // (n & 7) == g
                b[nt][0] = Ws[n * BK + cL];
                b[nt][1] = Ws[n * BK + cH];
            }
            #pragma unroll
            for (int mt = 0; mt < 4; mt++) {
                int m = wm + mt * 16 + g;      // (m & 7) == g
                uint32_t a[4];
                a[0] = As[m * BK + cL];
                a[1] = As[(m + 8) * BK + cL];
                a[2] = As[m * BK + cH];
                a[3] = As[(m + 8) * BK + cH];
                mma_tf32(acc[mt][0], a, b[0]);
                mma_tf32(acc[mt][1], a, b[1]);
            }
        }
        __syncthreads();
    }

    // ---- epilogues ----
    float bv[2][2];
    #pragma unroll
    for (int nt = 0; nt < 2; nt++) {
        int col = nb0 + wn + nt * 8 + 2 * t4;
        float2 bb = *(const float2*)&bias[col];
        bv[nt][0] = bb.x; bv[nt][1] = bb.y;
    }

    if (EPI == 0 || EPI == 2) {
        #pragma unroll
        for (int mt = 0; mt < 4; mt++) {
            int r0 = row0 + wm + mt * 16 + g;
            #pragma unroll
            for (int nt = 0; nt < 2; nt++) {
                int col = nb0 + wn + nt * 8 + 2 * t4;
                if (r0 < M) {
                    float o0 = acc[mt][nt][0] + bv[nt][0];
                    float o1 = acc[mt][nt][1] + bv[nt][1];
                    if (EPI == 2) {
                        float2 rr = *(const float2*)&residual[(size_t)r0 * ldc + col];
                        o0 += rr.x; o1 += rr.y;
                    }
                    *(float2*)&C[(size_t)r0 * ldc + col] = make_float2(o0, o1);
                }
                int r1 = r0 + 8;
                if (r1 < M) {
                    float o2 = acc[mt][nt][2] + bv[nt][0];
                    float o3 = acc[mt][nt][3] + bv[nt][1];
                    if (EPI == 2) {
                        float2 rr = *(const float2*)&residual[(size_t)r1 * ldc + col];
                        o2 += rr.x; o3 += rr.y;
                    }
                    *(float2*)&C[(size_t)r1 * ldc + col] = make_float2(o2, o3);
                }
            }
        }
    } else if (EPI == 3) {
        #pragma unroll
        for (int mt = 0; mt < 4; mt++) {
            int e0 = row0 + wm + mt * 16 + g;
            int e1 = e0 + 8;
            int s0 = g_src[e0], d0 = g_dst[e0];
            int s1 = g_src[e1], d1 = g_dst[e1];
            float p0 = 0.f, p1 = 0.f;
            #pragma unroll
            for (int nt = 0; nt < 2; nt++) {
                int col = nb0 + wn + nt * 8 + 2 * t4;
                float2 q0 = *(const float2*)&g_q[(size_t)d0 * H + col];
                float2 k0 = *(const float2*)&g_k[(size_t)s0 * H + col];
                float2 q1 = *(const float2*)&g_q[(size_t)d1 * H + col];
                float2 k1 = *(const float2*)&g_k[(size_t)s1 * H + col];
                p0 += silu(acc[mt][nt][0] + bv[nt][0]) * q0.x * k0.x
                    + silu(acc[mt][nt][1] + bv[nt][1]) * q0.y * k0.y;
                p1 += silu(acc[mt][nt][2] + bv[nt][0]) * q1.x * k1.x
                    + silu(acc[mt][nt][3] + bv[nt][1]) * q1.y * k1.y;
            }
            p0 += __shfl_xor_sync(0xffffffffu, p0, 1);
            p0 += __shfl_xor_sync(0xffffffffu, p0, 2);
            p1 += __shfl_xor_sync(0xffffffffu, p1, 1);
            p1 += __shfl_xor_sync(0xffffffffu, p1, 2);
            if (t4 == 0) {
                atomicAdd(&g_attn[e0], p0);
                atomicAdd(&g_attn[e1], p1);
            }
        }
    } else { // EPI == 4
        #pragma unroll
        for (int mt = 0; mt < 4; mt++) {
            int e0 = row0 + wm + mt * 16 + g;
            int e1 = e0 + 8;
            int s0 = g_src[e0], d0 = g_dst[e0];
            int s1 = g_src[e1], d1 = g_dst[e1];
            float sc0 = g_s[e0], sc1 = g_s[e1];
            #pragma unroll
            for (int nt = 0; nt < 2; nt++) {
                int col = nb0 + wn + nt * 8 + 2 * t4;
                float2 v0 = *(const float2*)&g_v[(size_t)s0 * H + col];
                float2 v1 = *(const float2*)&g_v[(size_t)s1 * H + col];
                float m00 = silu(acc[mt][nt][0] + bv[nt][0]) * sc0 * v0.x;
                float m01 = silu(acc[mt][nt][1] + bv[nt][1]) * sc0 * v0.y;
                float m10 = silu(acc[mt][nt][2] + bv[nt][0]) * sc1 * v1.x;
                float m11 = silu(acc[mt][nt][3] + bv[nt][1]) * sc1 * v1.y;
                asm volatile("red.global.add.v2.f32 [%0], {%1, %2};"
                             :: "l"(g_agg + (size_t)d0 * H + col),
                                "f"(m00), "f"(m01) : "memory");
                asm volatile("red.global.add.v2.f32 [%0], {%1, %2};"
                             :: "l"(g_agg + (size_t)d1 * H + col),
                                "f"(m10), "f"(m11) : "memory");
            }
        }
    }
}

// ---------------- attn -> s : silu(attn) * cosine cutoff ---------------------
__global__ void attn_post_kernel(const float* __restrict__ ew)
{
    int e = blockIdx.x * blockDim.x + threadIdx.x;
    if (e >= E_EDGES) return;
    float a = g_attn[e];
    float r = ew[e];
    float cut = (r < 5.0f) ? 0.5f * (cosf(r * 0.62831853071795864769f) + 1.0f) : 0.0f;
    g_s[e] = a / (1.f + __expf(-a)) * cut;
}

// ---------------- launch -----------------------------------------------------
extern "C" void kernel_launch(void* const* d_in, const int* in_sizes, int n_in,
                              void* d_out, int out_size)
{
    const float* x    = (const float*)d_in[0];
    const void*  eidx = (const void*)d_in[1];
    const float* ew   = (const float*)d_in[2];
    const float* ea   = (const float*)d_in[3];
    const float* ln_g = (const float*)d_in[4];
    const float* ln_b = (const float*)d_in[5];
    const float* Wq   = (const float*)d_in[6],  *bq  = (const float*)d_in[7];
    const float* Wk   = (const float*)d_in[8],  *bk  = (const float*)d_in[9];
    const float* Wv   = (const float*)d_in[10], *bv  = (const float*)d_in[11];
    const float* Wo   = (const float*)d_in[12], *bo  = (const float*)d_in[13];
    const float* Wdk  = (const float*)d_in[14], *bdk = (const float*)d_in[15];
    const float* Wdv  = (const float*)d_in[16], *bdv = (const float*)d_in[17];
    float* out = (float*)d_out;

    float *xn, *q, *k, *v, *agg;
    cudaGetSymbolAddress((void**)&xn,  g_xnorm);
    cudaGetSymbolAddress((void**)&q,   g_q);
    cudaGetSymbolAddress((void**)&k,   g_k);
    cudaGetSymbolAddress((void**)&v,   g_v);
    cudaGetSymbolAddress((void**)&agg, g_agg);

    // 0. edge_index dtype detection + int32 conversion (+ zero attn)
    detect_idx_kernel<<<1, 32>>>((const int*)eidx);
    convert_idx_kernel<<<(E_EDGES + 255) / 256, 256>>>(eidx);

    // 1. LayerNorm + zero agg
    ln_kernel<<<N_NODES, 256>>>(x, ln_g, ln_b);

    // 2. q, k, v = xn @ W^T + b
    dim3 gq((N_NODES + 127) / 128, H / 64);
    gemm_tf32<0><<<gq, 256>>>(xn, N_NODES, H, Wq, bq, q, H, nullptr);
    gemm_tf32<0><<<gq, 256>>>(xn, N_NODES, H, Wk, bk, k, H, nullptr);
    gemm_tf32<0><<<gq, 256>>>(xn, N_NODES, H, Wv, bv, v, H, nullptr);

    // 3. fused dk-GEMM + attention dot -> g_attn
    dim3 ge(E_EDGES / 128, H / 64);
    gemm_tf32<3><<<ge, 256>>>(ea, E_EDGES, R_RBF, Wdk, bdk, nullptr, 0, nullptr);

    // 4. s = silu(attn) * cutoff
    attn_post_kernel<<<(E_EDGES + 255) / 256, 256>>>(ew);

    // 5. fused dv-GEMM + message scatter -> g_agg
    gemm_tf32<4><<<ge, 256>>>(ea, E_EDGES, R_RBF, Wdv, bdv, nullptr, 0, nullptr);

    // 6. out = agg @ Wo^T + bo + x
    gemm_tf32<2><<<gq, 256>>>(agg, N_NODES, H, Wo, bo, out, H, x);
}